// round 1
// baseline (speedup 1.0000x reference)
#include <cuda_runtime.h>
#include <math.h>

#define NN 65536
#define EE 2097152
#define EGG 524288
#define BB 1024

// ---------------- scratch (device globals; allocation-free) ----------------
__device__ __align__(16) float g_h[NN * 128];
__device__ __align__(16) float g_ta[NN * 128];
__device__ __align__(16) float g_tg[NN * 128];
__device__ __align__(16) float g_aa[NN * 128];
__device__ __align__(16) float g_ag[NN * 128];
__device__ __align__(16) float g_s1[NN], g_r1[NN], g_s2[NN], g_r2[NN];
__device__ __align__(16) float g_v0[BB * 128], g_v1[BB * 128];
__device__ int g_sdeg[NN], g_rdeg[NN], g_gsd[NN], g_grd[NN];
__device__ int g_offm[NN], g_offg[NN], g_curm[NN], g_curg[NN];
__device__ int g_srcm[EE], g_srcg[EGG];
__device__ int g_yi[NN], g_bsum[64];

// ---------------- f32x2 helpers ----------------
__device__ __forceinline__ unsigned long long pack2(float x) {
    unsigned long long r;
    unsigned u = __float_as_uint(x);
    asm("mov.b64 %0, {%1, %1};" : "=l"(r) : "r"(u));
    return r;
}
__device__ __forceinline__ void fma2(unsigned long long& d, unsigned long long a,
                                     unsigned long long b) {
    asm("fma.rn.f32x2 %0, %1, %2, %0;" : "+l"(d) : "l"(a), "l"(b));
}
__device__ __forceinline__ float2 unpack2(unsigned long long v) {
    unsigned lo, hi;
    asm("mov.b64 {%0, %1}, %2;" : "=r"(lo), "=r"(hi) : "l"(v));
    float2 f;
    f.x = __uint_as_float(lo);
    f.y = __uint_as_float(hi);
    return f;
}

// ---------------- GEMM: out[r,c] = act((A[r,:] (*rsA[r]) @ W + [A2*rsA2 @ W2]) + bias) (* oscale[r])
// A: [nrows,128], W: [128,128] row-major (K-major). nrows multiple of 64.
#define GEMM_SMEM ((128 * 68 + 128 * 128) * 4)

__global__ void __launch_bounds__(256, 2) gemm128(
    const float* __restrict__ A, const float* __restrict__ rsA,
    const float* __restrict__ A2, const float* __restrict__ rsA2,
    const float* __restrict__ W, const float* __restrict__ W2,
    const float* __restrict__ bias, const float* __restrict__ oscale,
    float* __restrict__ out, int dual, int relu)
{
    extern __shared__ float sm[];
    float* Ast = sm;              // [128][68]  A tile transposed (k-major)
    float* Ws = sm + 128 * 68;    // [128][128]
    const int tid = threadIdx.x;
    const int tx = tid & 15;      // 16 col groups: cols {4tx..4tx+3} and {64+4tx..}
    const int ty = tid >> 4;      // 16 row groups of 4 rows
    const int row0 = blockIdx.x * 64;

    unsigned long long acc[4][4];
#pragma unroll
    for (int i = 0; i < 4; ++i)
#pragma unroll
        for (int j = 0; j < 4; ++j) acc[i][j] = 0ull;

    for (int stage = 0; stage <= dual; ++stage) {
        const float* Ac = stage ? A2 : A;
        const float* rs = stage ? rsA2 : rsA;
        const float* Wc = stage ? W2 : W;
        if (stage) __syncthreads();
        {
            int r = tid & 63;
            int k4b = tid >> 6;  // 0..3
            float rsv = rs ? rs[row0 + r] : 1.0f;
#pragma unroll
            for (int p = 0; p < 8; ++p) {
                int k4 = k4b + p * 4;  // 0..31
                float4 v = ((const float4*)Ac)[(size_t)(row0 + r) * 32 + k4];
                v.x *= rsv; v.y *= rsv; v.z *= rsv; v.w *= rsv;
                // transpose store: lanes vary r (stride-1) -> conflict free
                Ast[(k4 * 4 + 0) * 68 + r] = v.x;
                Ast[(k4 * 4 + 1) * 68 + r] = v.y;
                Ast[(k4 * 4 + 2) * 68 + r] = v.z;
                Ast[(k4 * 4 + 3) * 68 + r] = v.w;
            }
        }
#pragma unroll
        for (int p = 0; p < 16; ++p) {
            int i = tid + p * 256;  // 4096 float4
            ((float4*)Ws)[i] = ((const float4*)Wc)[i];
        }
        __syncthreads();

        const ulonglong2* Wu = (const ulonglong2*)Ws;  // 32 per row
#pragma unroll 8
        for (int k = 0; k < 128; ++k) {
            float4 a4 = *(const float4*)(Ast + k * 68 + ty * 4);
            ulonglong2 q0 = Wu[k * 32 + tx];        // cols 4tx..4tx+3
            ulonglong2 q1 = Wu[k * 32 + 16 + tx];   // cols 64+4tx..
            unsigned long long ap[4];
            ap[0] = pack2(a4.x); ap[1] = pack2(a4.y);
            ap[2] = pack2(a4.z); ap[3] = pack2(a4.w);
#pragma unroll
            for (int rr = 0; rr < 4; ++rr) {
                fma2(acc[rr][0], ap[rr], q0.x);
                fma2(acc[rr][1], ap[rr], q0.y);
                fma2(acc[rr][2], ap[rr], q1.x);
                fma2(acc[rr][3], ap[rr], q1.y);
            }
        }
    }

    float bb[8];
#pragma unroll
    for (int j = 0; j < 4; ++j) {
        bb[j] = bias[tx * 4 + j];
        bb[4 + j] = bias[64 + tx * 4 + j];
    }
#pragma unroll
    for (int rr = 0; rr < 4; ++rr) {
        int r = row0 + ty * 4 + rr;
        float sc = oscale ? oscale[r] : 1.0f;
        float2 p0 = unpack2(acc[rr][0]);
        float2 p1 = unpack2(acc[rr][1]);
        float2 p2 = unpack2(acc[rr][2]);
        float2 p3 = unpack2(acc[rr][3]);
        float4 o0 = make_float4((p0.x + bb[0]) * sc, (p0.y + bb[1]) * sc,
                                (p1.x + bb[2]) * sc, (p1.y + bb[3]) * sc);
        float4 o1 = make_float4((p2.x + bb[4]) * sc, (p2.y + bb[5]) * sc,
                                (p3.x + bb[6]) * sc, (p3.y + bb[7]) * sc);
        if (relu) {
            o0.x = fmaxf(o0.x, 0.f); o0.y = fmaxf(o0.y, 0.f);
            o0.z = fmaxf(o0.z, 0.f); o0.w = fmaxf(o0.w, 0.f);
            o1.x = fmaxf(o1.x, 0.f); o1.y = fmaxf(o1.y, 0.f);
            o1.z = fmaxf(o1.z, 0.f); o1.w = fmaxf(o1.w, 0.f);
        }
        ((float4*)out)[(size_t)r * 32 + tx] = o0;
        ((float4*)out)[(size_t)r * 32 + 16 + tx] = o1;
    }
}

// ---------------- graph preprocessing ----------------
__global__ void deg_kernel(const int* __restrict__ snd, const int* __restrict__ rcv,
                           int* sdeg, int* rdeg, int ne)
{
    int e = blockIdx.x * blockDim.x + threadIdx.x;
    if (e >= ne) return;
    atomicAdd(&sdeg[snd[e]], 1);
    atomicAdd(&rdeg[rcv[e]], 1);
}

__global__ void norm_kernel(const int* __restrict__ sdeg, const int* __restrict__ rdeg,
                            float* __restrict__ s, float* __restrict__ r)
{
    int i = blockIdx.x * blockDim.x + threadIdx.x;
    if (i >= NN) return;
    s[i] = rsqrtf((float)(sdeg[i] + 1));  // +1 self edge
    r[i] = rsqrtf((float)(rdeg[i] + 1));
}

__global__ void scan_block(const int* __restrict__ x, int* __restrict__ y,
                           int* __restrict__ bsum)
{
    __shared__ int smv[1024];
    int i = blockIdx.x * 1024 + threadIdx.x;
    smv[threadIdx.x] = x[i];
    __syncthreads();
    for (int d = 1; d < 1024; d <<= 1) {
        int t = (threadIdx.x >= d) ? smv[threadIdx.x - d] : 0;
        __syncthreads();
        smv[threadIdx.x] += t;
        __syncthreads();
    }
    y[i] = smv[threadIdx.x];
    if (threadIdx.x == 1023) bsum[blockIdx.x] = smv[1023];
}

__global__ void scan_top64(int* bsum)
{
    __shared__ int smv[64];
    smv[threadIdx.x] = bsum[threadIdx.x];
    __syncthreads();
    for (int d = 1; d < 64; d <<= 1) {
        int t = (threadIdx.x >= d) ? smv[threadIdx.x - d] : 0;
        __syncthreads();
        smv[threadIdx.x] += t;
        __syncthreads();
    }
    bsum[threadIdx.x] = smv[threadIdx.x];
}

__global__ void finalize_off(const int* __restrict__ x, const int* __restrict__ y,
                             const int* __restrict__ bsum, int* __restrict__ off)
{
    int i = blockIdx.x * 1024 + threadIdx.x;
    int b = blockIdx.x;
    off[i] = y[i] - x[i] + (b ? bsum[b - 1] : 0);  // exclusive scan
}

__global__ void fill_csr(const int* __restrict__ snd, const int* __restrict__ rcv,
                         const int* __restrict__ off, int* __restrict__ cur,
                         int* __restrict__ src, int ne)
{
    int e = blockIdx.x * blockDim.x + threadIdx.x;
    if (e >= ne) return;
    int r = rcv[e];
    int p = off[r] + atomicAdd(&cur[r], 1);
    src[p] = snd[e];
}

// ---------------- embed ----------------
__global__ void embed_kernel(const int* __restrict__ nodes,
                             const float* __restrict__ emb, float* __restrict__ h)
{
    int t = blockIdx.x * blockDim.x + threadIdx.x;  // NN*32
    int row = t >> 5, c = t & 31;
    ((float4*)h)[t] = ((const float4*)emb)[nodes[row] * 32 + c];
}

// ---------------- CSR gather aggregation: out[i] = t[i] + sum_{e in CSR(i)} t[src[e]]
__global__ void agg_kernel(const float* __restrict__ t, const int* __restrict__ off,
                           const int* __restrict__ cnt, const int* __restrict__ src,
                           float* __restrict__ out)
{
    int w = (blockIdx.x * blockDim.x + threadIdx.x) >> 5;
    int lane = threadIdx.x & 31;
    if (w >= NN) return;
    const float4* t4 = (const float4*)t;
    float4 s = t4[(size_t)w * 32 + lane];  // self edge
    int beg = off[w], n = cnt[w];
    int j = 0;
    for (; j + 4 <= n; j += 4) {
        int s0 = src[beg + j], s1 = src[beg + j + 1];
        int s2 = src[beg + j + 2], s3 = src[beg + j + 3];
        float4 v0 = t4[(size_t)s0 * 32 + lane];
        float4 v1 = t4[(size_t)s1 * 32 + lane];
        float4 v2 = t4[(size_t)s2 * 32 + lane];
        float4 v3 = t4[(size_t)s3 * 32 + lane];
        s.x += v0.x + v1.x + v2.x + v3.x;
        s.y += v0.y + v1.y + v2.y + v3.y;
        s.z += v0.z + v1.z + v2.z + v3.z;
        s.w += v0.w + v1.w + v2.w + v3.w;
    }
    for (; j < n; ++j) {
        int si = src[beg + j];
        float4 v = t4[(size_t)si * 32 + lane];
        s.x += v.x; s.y += v.y; s.z += v.z; s.w += v.w;
    }
    ((float4*)out)[(size_t)w * 32 + lane] = s;
}

// ---------------- logits: out[e] = dot(lg[snd[e]], lg[rcv[e]]) ----------------
__global__ void logits_kernel(const float* __restrict__ lg, const int* __restrict__ snd,
                              const int* __restrict__ rcv, float* __restrict__ out)
{
    int t = blockIdx.x * blockDim.x + threadIdx.x;
    int e = t >> 3, g = t & 7;  // 8 lanes per edge, 16 floats each
    if (e >= EE) return;
    int s = snd[e], r = rcv[e];
    const float4* a = (const float4*)lg + (size_t)s * 32 + g * 4;
    const float4* b = (const float4*)lg + (size_t)r * 32 + g * 4;
    float acc = 0.f;
#pragma unroll
    for (int i = 0; i < 4; ++i) {
        float4 x = a[i], y = b[i];
        acc += x.x * y.x + x.y * y.y + x.z * y.z + x.w * y.w;
    }
    acc += __shfl_down_sync(0xffffffffu, acc, 4);
    acc += __shfl_down_sync(0xffffffffu, acc, 2);
    acc += __shfl_down_sync(0xffffffffu, acc, 1);
    if (g == 0) out[e] = acc;
}

// ---------------- eval head ----------------
__global__ void pool_kernel(const float* __restrict__ h, float* __restrict__ v)
{
    int b = blockIdx.x, c = threadIdx.x;  // 128 threads
    float s = 0.f;
    for (int j = 1; j < 64; ++j) s += h[((size_t)b * 64 + j) * 128 + c];
    v[b * 128 + c] = s * (1.0f / 63.0f);
}

__global__ void head_kernel(const float* __restrict__ v, const float* __restrict__ wout,
                            const float* __restrict__ bout, float* __restrict__ out)
{
    int t = blockIdx.x * blockDim.x + threadIdx.x;
    int b = t >> 5, lane = t & 31;
    if (b >= BB) return;
    float4 x = ((const float4*)v)[b * 32 + lane];
    float4 w = ((const float4*)wout)[lane];
    float acc = x.x * w.x + x.y * w.y + x.z * w.z + x.w * w.w;
#pragma unroll
    for (int o = 16; o; o >>= 1) acc += __shfl_down_sync(0xffffffffu, acc, o);
    if (lane == 0) out[b] = tanhf(acc + bout[0]);
}

// ---------------- host ----------------
extern "C" void kernel_launch(void* const* d_in, const int* in_sizes, int n_in,
                              void* d_out, int out_size)
{
    (void)in_sizes; (void)n_in; (void)out_size;
    const int* nodes = (const int*)d_in[0];
    const int* snd = (const int*)d_in[1];
    const int* rcv = (const int*)d_in[2];
    const int* gsnd = (const int*)d_in[3];
    const int* grcv = (const int*)d_in[4];
    // d_in[5] = n_node (constant 64, unused)
    const float* emb = (const float*)d_in[6];
    const float* w1 = (const float*)d_in[7];
    const float* b1 = (const float*)d_in[8];
    const float* w2 = (const float*)d_in[9];
    const float* b2 = (const float*)d_in[10];
    const float* w3 = (const float*)d_in[11];
    const float* b3 = (const float*)d_in[12];
    const float* wl = (const float*)d_in[13];
    const float* bl = (const float*)d_in[14];
    const float* ew = (const float*)d_in[15];
    const float* eb = (const float*)d_in[16];
    const float* wo = (const float*)d_in[17];
    const float* bo = (const float*)d_in[18];
    float* out = (float*)d_out;

    float *h, *ta, *tg, *aa, *ag, *s1, *r1, *s2, *r2, *v0, *v1;
    int *sdeg, *rdeg, *gsd, *grd, *offm, *offg, *curm, *curg, *srcm, *srcg, *yi, *bsum;
    cudaGetSymbolAddress((void**)&h, g_h);
    cudaGetSymbolAddress((void**)&ta, g_ta);
    cudaGetSymbolAddress((void**)&tg, g_tg);
    cudaGetSymbolAddress((void**)&aa, g_aa);
    cudaGetSymbolAddress((void**)&ag, g_ag);
    cudaGetSymbolAddress((void**)&s1, g_s1);
    cudaGetSymbolAddress((void**)&r1, g_r1);
    cudaGetSymbolAddress((void**)&s2, g_s2);
    cudaGetSymbolAddress((void**)&r2, g_r2);
    cudaGetSymbolAddress((void**)&v0, g_v0);
    cudaGetSymbolAddress((void**)&v1, g_v1);
    cudaGetSymbolAddress((void**)&sdeg, g_sdeg);
    cudaGetSymbolAddress((void**)&rdeg, g_rdeg);
    cudaGetSymbolAddress((void**)&gsd, g_gsd);
    cudaGetSymbolAddress((void**)&grd, g_grd);
    cudaGetSymbolAddress((void**)&offm, g_offm);
    cudaGetSymbolAddress((void**)&offg, g_offg);
    cudaGetSymbolAddress((void**)&curm, g_curm);
    cudaGetSymbolAddress((void**)&curg, g_curg);
    cudaGetSymbolAddress((void**)&srcm, g_srcm);
    cudaGetSymbolAddress((void**)&srcg, g_srcg);
    cudaGetSymbolAddress((void**)&yi, g_yi);
    cudaGetSymbolAddress((void**)&bsum, g_bsum);

    cudaFuncSetAttribute(gemm128, cudaFuncAttributeMaxDynamicSharedMemorySize, GEMM_SMEM);

    cudaMemsetAsync(sdeg, 0, NN * sizeof(int));
    cudaMemsetAsync(rdeg, 0, NN * sizeof(int));
    cudaMemsetAsync(gsd, 0, NN * sizeof(int));
    cudaMemsetAsync(grd, 0, NN * sizeof(int));
    cudaMemsetAsync(curm, 0, NN * sizeof(int));
    cudaMemsetAsync(curg, 0, NN * sizeof(int));

    deg_kernel<<<EE / 256, 256>>>(snd, rcv, sdeg, rdeg, EE);
    deg_kernel<<<EGG / 256, 256>>>(gsnd, grcv, gsd, grd, EGG);
    norm_kernel<<<NN / 256, 256>>>(sdeg, rdeg, s1, r1);
    norm_kernel<<<NN / 256, 256>>>(gsd, grd, s2, r2);

    // CSR for move edges (receiver-sorted)
    scan_block<<<64, 1024>>>(rdeg, yi, bsum);
    scan_top64<<<1, 64>>>(bsum);
    finalize_off<<<64, 1024>>>(rdeg, yi, bsum, offm);
    fill_csr<<<EE / 256, 256>>>(snd, rcv, offm, curm, srcm, EE);

    // CSR for grid edges
    scan_block<<<64, 1024>>>(grd, yi, bsum);
    scan_top64<<<1, 64>>>(bsum);
    finalize_off<<<64, 1024>>>(grd, yi, bsum, offg);
    fill_csr<<<EGG / 256, 256>>>(gsnd, grcv, offg, curg, srcg, EGG);

    embed_kernel<<<NN * 32 / 256, 256>>>(nodes, emb, h);

    for (int i = 0; i < 7; ++i) {
        const float* W1 = w1 + (size_t)i * 128 * 128;
        const float* W2 = w2 + (size_t)i * 128 * 128;
        const float* W3 = w3 + (size_t)i * 256 * 128;
        gemm128<<<NN / 64, 256, GEMM_SMEM>>>(h, 0, 0, 0, W1, 0, b1 + i * 128, s1, ta, 0, 0);
        gemm128<<<NN / 64, 256, GEMM_SMEM>>>(h, 0, 0, 0, W2, 0, b2 + i * 128, s2, tg, 0, 0);
        agg_kernel<<<NN * 32 / 256, 256>>>(ta, offm, rdeg, srcm, aa);
        agg_kernel<<<NN * 32 / 256, 256>>>(tg, offg, grd, srcg, ag);
        gemm128<<<NN / 64, 256, GEMM_SMEM>>>(aa, r1, ag, r2, W3, W3 + 128 * 128,
                                             b3 + i * 128, 0, h, 1, 1);
    }

    // logit projection (reuse ta as lg) + edge dots
    gemm128<<<NN / 64, 256, GEMM_SMEM>>>(h, 0, 0, 0, wl, 0, bl, 0, ta, 0, 0);
    logits_kernel<<<EE * 8 / 256, 256>>>(ta, snd, rcv, out);

    // eval head
    pool_kernel<<<BB, 128>>>(h, v0);
    float* vin = v0;
    float* vout = v1;
    for (int i = 0; i < 5; ++i) {
        gemm128<<<BB / 64, 256, GEMM_SMEM>>>(vin, 0, 0, 0, ew + (size_t)i * 128 * 128, 0,
                                             eb + i * 128, 0, vout, 0, 1);
        float* t = vout; vout = vin; vin = t;
    }
    head_kernel<<<BB * 32 / 256, 256>>>(vin, wo, bo, out + EE);
}

// round 4
// speedup vs baseline: 1.0361x; 1.0361x over previous
#include <cuda_runtime.h>
#include <math.h>

#define NN 65536
#define EE 2097152
#define EGG 524288
#define BB 1024

// ---------------- scratch (device globals; allocation-free) ----------------
__device__ __align__(16) float g_h[NN * 128];
__device__ __align__(16) float g_ta[NN * 128];
__device__ __align__(16) float g_aa[NN * 128];
__device__ __align__(16) float g_ag[NN * 128];
__device__ __align__(16) float g_s1[NN], g_r1[NN], g_s2[NN], g_r2[NN];
__device__ __align__(16) float g_c1[NN], g_c2[NN];
__device__ __align__(16) float g_w13[7 * 128 * 128];
__device__ __align__(16) float g_w23[7 * 128 * 128];
__device__ __align__(16) float g_bv1[7 * 128], g_bv2[7 * 128];
__device__ int g_sdeg[NN], g_rdeg[NN], g_gsd[NN], g_grd[NN];
__device__ int g_offm[NN], g_offg[NN], g_curm[NN], g_curg[NN];
__device__ int g_srcm[EE], g_srcg[EGG];

// ---------------- f32x2 helpers ----------------
__device__ __forceinline__ unsigned long long pack2(float x) {
    unsigned long long r;
    unsigned u = __float_as_uint(x);
    asm("mov.b64 %0, {%1, %1};" : "=l"(r) : "r"(u));
    return r;
}
__device__ __forceinline__ void fma2(unsigned long long& d, unsigned long long a,
                                     unsigned long long b) {
    asm("fma.rn.f32x2 %0, %1, %2, %0;" : "+l"(d) : "l"(a), "l"(b));
}
__device__ __forceinline__ float2 unpack2(unsigned long long v) {
    unsigned lo, hi;
    asm("mov.b64 {%0, %1}, %2;" : "=r"(lo), "=r"(hi) : "l"(v));
    float2 f;
    f.x = __uint_as_float(lo);
    f.y = __uint_as_float(hi);
    return f;
}

// ---------------- GEMM ----------------
// out[r,:] = act( (rsA[r]*A[r,:])@W + [ (rsA2[r]*A2[r,:])@W2 ]
//                 + bias + cr1[r]*bv1 + cr2[r]*bv2 )
#define GEMM_SMEM ((128 * 68 + 128 * 128) * 4)

__global__ void __launch_bounds__(256, 2) gemm128(
    const float* __restrict__ A, const float* __restrict__ rsA,
    const float* __restrict__ A2, const float* __restrict__ rsA2,
    const float* __restrict__ W, const float* __restrict__ W2,
    const float* __restrict__ bias,
    const float* __restrict__ bv1, const float* __restrict__ bv2,
    const float* __restrict__ cr1, const float* __restrict__ cr2,
    float* __restrict__ out, int dual, int relu)
{
    extern __shared__ float sm[];
    float* Ast = sm;              // [128][68]  A tile transposed (k-major)
    float* Ws = sm + 128 * 68;    // [128][128]
    const int tid = threadIdx.x;
    const int tx = tid & 15;
    const int ty = tid >> 4;
    const int row0 = blockIdx.x * 64;

    unsigned long long acc[4][4];
#pragma unroll
    for (int i = 0; i < 4; ++i)
#pragma unroll
        for (int j = 0; j < 4; ++j) acc[i][j] = 0ull;

    for (int stage = 0; stage <= dual; ++stage) {
        const float* Ac = stage ? A2 : A;
        const float* rs = stage ? rsA2 : rsA;
        const float* Wc = stage ? W2 : W;
        if (stage) __syncthreads();
        {
            int r = tid & 63;
            int k4b = tid >> 6;
            float rsv = rs ? rs[row0 + r] : 1.0f;
#pragma unroll
            for (int p = 0; p < 8; ++p) {
                int k4 = k4b + p * 4;
                float4 v = ((const float4*)Ac)[(size_t)(row0 + r) * 32 + k4];
                v.x *= rsv; v.y *= rsv; v.z *= rsv; v.w *= rsv;
                Ast[(k4 * 4 + 0) * 68 + r] = v.x;
                Ast[(k4 * 4 + 1) * 68 + r] = v.y;
                Ast[(k4 * 4 + 2) * 68 + r] = v.z;
                Ast[(k4 * 4 + 3) * 68 + r] = v.w;
            }
        }
#pragma unroll
        for (int p = 0; p < 16; ++p) {
            int i = tid + p * 256;
            ((float4*)Ws)[i] = ((const float4*)Wc)[i];
        }
        __syncthreads();

        const ulonglong2* Wu = (const ulonglong2*)Ws;
#pragma unroll 8
        for (int k = 0; k < 128; ++k) {
            float4 a4 = *(const float4*)(Ast + k * 68 + ty * 4);
            ulonglong2 q0 = Wu[k * 32 + tx];
            ulonglong2 q1 = Wu[k * 32 + 16 + tx];
            unsigned long long ap[4];
            ap[0] = pack2(a4.x); ap[1] = pack2(a4.y);
            ap[2] = pack2(a4.z); ap[3] = pack2(a4.w);
#pragma unroll
            for (int rr = 0; rr < 4; ++rr) {
                fma2(acc[rr][0], ap[rr], q0.x);
                fma2(acc[rr][1], ap[rr], q0.y);
                fma2(acc[rr][2], ap[rr], q1.x);
                fma2(acc[rr][3], ap[rr], q1.y);
            }
        }
    }

    float bb[8], v1[8], v2[8];
#pragma unroll
    for (int j = 0; j < 4; ++j) {
        bb[j] = bias[tx * 4 + j];
        bb[4 + j] = bias[64 + tx * 4 + j];
        v1[j] = bv1 ? bv1[tx * 4 + j] : 0.f;
        v1[4 + j] = bv1 ? bv1[64 + tx * 4 + j] : 0.f;
        v2[j] = bv2 ? bv2[tx * 4 + j] : 0.f;
        v2[4 + j] = bv2 ? bv2[64 + tx * 4 + j] : 0.f;
    }
#pragma unroll
    for (int rr = 0; rr < 4; ++rr) {
        int r = row0 + ty * 4 + rr;
        float c1 = cr1 ? cr1[r] : 0.f;
        float c2 = cr2 ? cr2[r] : 0.f;
        float2 p0 = unpack2(acc[rr][0]);
        float2 p1 = unpack2(acc[rr][1]);
        float2 p2 = unpack2(acc[rr][2]);
        float2 p3 = unpack2(acc[rr][3]);
        float o[8] = {p0.x, p0.y, p1.x, p1.y, p2.x, p2.y, p3.x, p3.y};
#pragma unroll
        for (int j = 0; j < 8; ++j) {
            o[j] += bb[j] + c1 * v1[j] + c2 * v2[j];
            if (relu) o[j] = fmaxf(o[j], 0.f);
        }
        ((float4*)out)[(size_t)r * 32 + tx] = make_float4(o[0], o[1], o[2], o[3]);
        ((float4*)out)[(size_t)r * 32 + 16 + tx] = make_float4(o[4], o[5], o[6], o[7]);
    }
}

// ---------------- graph preprocessing ----------------
__global__ void deg_both(const int* __restrict__ snd, const int* __restrict__ rcv,
                         const int* __restrict__ gsnd, const int* __restrict__ grcv,
                         int* sdeg, int* rdeg, int* gsd, int* grd)
{
    int e = blockIdx.x * blockDim.x + threadIdx.x;
    if (e < EE) {
        atomicAdd(&sdeg[snd[e]], 1);
        atomicAdd(&rdeg[rcv[e]], 1);
    }
    if (e < EGG) {
        atomicAdd(&gsd[gsnd[e]], 1);
        atomicAdd(&grd[grcv[e]], 1);
    }
}

__global__ void norm_both(const int* __restrict__ sdeg, const int* __restrict__ rdeg,
                          const int* __restrict__ gsd, const int* __restrict__ grd,
                          float* s1, float* r1, float* s2, float* r2)
{
    int i = blockIdx.x * blockDim.x + threadIdx.x;
    if (i >= NN) return;
    s1[i] = rsqrtf((float)(sdeg[i] + 1));
    r1[i] = rsqrtf((float)(rdeg[i] + 1));
    s2[i] = rsqrtf((float)(gsd[i] + 1));
    r2[i] = rsqrtf((float)(grd[i] + 1));
}

__device__ void scan_one(const int* __restrict__ x, int* __restrict__ off, int* part)
{
    int t = threadIdx.x;
    int base = t * 64;
    int s = 0;
#pragma unroll 8
    for (int j = 0; j < 64; ++j) s += x[base + j];
    part[t] = s;
    __syncthreads();
    for (int d = 1; d < 1024; d <<= 1) {
        int v = (t >= d) ? part[t - d] : 0;
        __syncthreads();
        part[t] += v;
        __syncthreads();
    }
    int run = t ? part[t - 1] : 0;
#pragma unroll 8
    for (int j = 0; j < 64; ++j) {
        off[base + j] = run;
        run += x[base + j];
    }
    __syncthreads();
}

__global__ void scan_both(const int* rdeg, const int* grd, int* offm, int* offg)
{
    __shared__ int part[1024];
    scan_one(rdeg, offm, part);
    scan_one(grd, offg, part);
}

__global__ void fill_both(const int* __restrict__ snd, const int* __restrict__ rcv,
                          const int* __restrict__ gsnd, const int* __restrict__ grcv,
                          const int* __restrict__ offm, const int* __restrict__ offg,
                          int* curm, int* curg, int* srcm, int* srcg)
{
    int e = blockIdx.x * blockDim.x + threadIdx.x;
    if (e < EE) {
        int r = rcv[e];
        srcm[offm[r] + atomicAdd(&curm[r], 1)] = snd[e];
    }
    if (e < EGG) {
        int r = grcv[e];
        srcg[offg[r] + atomicAdd(&curg[r], 1)] = gsnd[e];
    }
}

// c1[i] = r1[i]*(s1[i] + sum_src s1[src]);  likewise grid
__global__ void csum_kernel(const float* __restrict__ s1, const float* __restrict__ r1,
                            const float* __restrict__ s2, const float* __restrict__ r2,
                            const int* __restrict__ offm, const int* __restrict__ cntm,
                            const int* __restrict__ srcm,
                            const int* __restrict__ offg, const int* __restrict__ cntg,
                            const int* __restrict__ srcg,
                            float* __restrict__ c1, float* __restrict__ c2)
{
    int i = blockIdx.x * blockDim.x + threadIdx.x;
    if (i >= NN) return;
    float a = s1[i];
    int b = offm[i], n = cntm[i];
    for (int j = 0; j < n; ++j) a += s1[srcm[b + j]];
    c1[i] = r1[i] * a;
    float g = s2[i];
    b = offg[i]; n = cntg[i];
    for (int j = 0; j < n; ++j) g += s2[srcg[b + j]];
    c2[i] = r2[i] * g;
}

// ---------------- embed ----------------
__global__ void embed_kernel(const int* __restrict__ nodes,
                             const float* __restrict__ emb, float* __restrict__ h)
{
    int t = blockIdx.x * blockDim.x + threadIdx.x;
    int row = t >> 5, c = t & 31;
    ((float4*)h)[t] = ((const float4*)emb)[nodes[row] * 32 + c];
}

// ---------------- fused dual-graph aggregation ----------------
// am[i] = s1[i]*h[i] + sum_src s1[src]*h[src];  ag likewise with s2/grid CSR
__global__ void agg2_kernel(const float* __restrict__ h,
                            const float* __restrict__ s1, const float* __restrict__ s2,
                            const int* __restrict__ offm, const int* __restrict__ cntm,
                            const int* __restrict__ srcm,
                            const int* __restrict__ offg, const int* __restrict__ cntg,
                            const int* __restrict__ srcg,
                            float* __restrict__ am, float* __restrict__ ag)
{
    int w = (blockIdx.x * blockDim.x + threadIdx.x) >> 5;
    int lane = threadIdx.x & 31;
    if (w >= NN) return;
    const float4* h4 = (const float4*)h;
    float4 hv = h4[(size_t)w * 32 + lane];
    float si = s1[w], gi = s2[w];
    float4 A = make_float4(hv.x * si, hv.y * si, hv.z * si, hv.w * si);
    float4 G = make_float4(hv.x * gi, hv.y * gi, hv.z * gi, hv.w * gi);

    int beg = offm[w], n = cntm[w];
    int j = 0;
    for (; j + 4 <= n; j += 4) {
        int i0 = srcm[beg + j], i1 = srcm[beg + j + 1];
        int i2 = srcm[beg + j + 2], i3 = srcm[beg + j + 3];
        float f0 = s1[i0], f1 = s1[i1], f2 = s1[i2], f3 = s1[i3];
        float4 v0 = h4[(size_t)i0 * 32 + lane];
        float4 v1 = h4[(size_t)i1 * 32 + lane];
        float4 v2 = h4[(size_t)i2 * 32 + lane];
        float4 v3 = h4[(size_t)i3 * 32 + lane];
        A.x += f0 * v0.x + f1 * v1.x + f2 * v2.x + f3 * v3.x;
        A.y += f0 * v0.y + f1 * v1.y + f2 * v2.y + f3 * v3.y;
        A.z += f0 * v0.z + f1 * v1.z + f2 * v2.z + f3 * v3.z;
        A.w += f0 * v0.w + f1 * v1.w + f2 * v2.w + f3 * v3.w;
    }
    for (; j < n; ++j) {
        int i0 = srcm[beg + j];
        float f0 = s1[i0];
        float4 v0 = h4[(size_t)i0 * 32 + lane];
        A.x += f0 * v0.x; A.y += f0 * v0.y; A.z += f0 * v0.z; A.w += f0 * v0.w;
    }

    beg = offg[w]; n = cntg[w];
    j = 0;
    for (; j + 2 <= n; j += 2) {
        int i0 = srcg[beg + j], i1 = srcg[beg + j + 1];
        float f0 = s2[i0], f1 = s2[i1];
        float4 v0 = h4[(size_t)i0 * 32 + lane];
        float4 v1 = h4[(size_t)i1 * 32 + lane];
        G.x += f0 * v0.x + f1 * v1.x;
        G.y += f0 * v0.y + f1 * v1.y;
        G.z += f0 * v0.z + f1 * v1.z;
        G.w += f0 * v0.w + f1 * v1.w;
    }
    for (; j < n; ++j) {
        int i0 = srcg[beg + j];
        float f0 = s2[i0];
        float4 v0 = h4[(size_t)i0 * 32 + lane];
        G.x += f0 * v0.x; G.y += f0 * v0.y; G.z += f0 * v0.z; G.w += f0 * v0.w;
    }
    ((float4*)am)[(size_t)w * 32 + lane] = A;
    ((float4*)ag)[(size_t)w * 32 + lane] = G;
}

// ---------------- weight precompute: W13 = W1@W3a, W23 = W2@W3b, bv = b@W3x ----
#define PREW_SMEM (128 * 128 * 4)
__global__ void precompute_w(const float* __restrict__ w1, const float* __restrict__ w2,
                             const float* __restrict__ w3,
                             const float* __restrict__ b1, const float* __restrict__ b2,
                             float* __restrict__ w13, float* __restrict__ w23,
                             float* __restrict__ bv1, float* __restrict__ bv2)
{
    extern __shared__ float Bs[];
    int layer = blockIdx.x >> 1;
    int which = blockIdx.x & 1;
    const float* Aw = (which ? w2 : w1) + (size_t)layer * 16384;
    const float* Bw = w3 + (size_t)layer * 32768 + which * 16384;
    const float* bb = (which ? b2 : b1) + layer * 128;
    float* Cw = (which ? w23 : w13) + (size_t)layer * 16384;
    float* bv = (which ? bv2 : bv1) + layer * 128;
    int t = threadIdx.x;
#pragma unroll
    for (int p = 0; p < 16; ++p)
        ((float4*)Bs)[t + p * 256] = ((const float4*)Bw)[t + p * 256];
    __syncthreads();
    int k = t >> 1;
    int c0 = (t & 1) * 64;
    float acc[64];
#pragma unroll
    for (int c = 0; c < 64; ++c) acc[c] = 0.f;
    for (int j = 0; j < 128; ++j) {
        float a = Aw[k * 128 + j];
        const float* br = Bs + j * 128 + c0;
#pragma unroll
        for (int c = 0; c < 64; ++c) acc[c] += a * br[c];
    }
#pragma unroll
    for (int c = 0; c < 64; ++c) Cw[k * 128 + c0 + c] = acc[c];
    if (t < 128) {
        float a = 0.f;
        for (int j = 0; j < 128; ++j) a += bb[j] * Bs[j * 128 + t];
        bv[t] = a;
    }
}

// ---------------- logits ----------------
__global__ void logits_kernel(const float* __restrict__ lg, const int* __restrict__ snd,
                              const int* __restrict__ rcv, float* __restrict__ out)
{
    int t = blockIdx.x * blockDim.x + threadIdx.x;
    int e = t >> 3, g = t & 7;
    if (e >= EE) return;
    int s = snd[e], r = rcv[e];
    const float4* a = (const float4*)lg + (size_t)s * 32 + g * 4;
    const float4* b = (const float4*)lg + (size_t)r * 32 + g * 4;
    float acc = 0.f;
#pragma unroll
    for (int i = 0; i < 4; ++i) {
        float4 x = a[i], y = b[i];
        acc += x.x * y.x + x.y * y.y + x.z * y.z + x.w * y.w;
    }
    acc += __shfl_down_sync(0xffffffffu, acc, 4);
    acc += __shfl_down_sync(0xffffffffu, acc, 2);
    acc += __shfl_down_sync(0xffffffffu, acc, 1);
    if (g == 0) out[e] = acc;
}

// ---------------- fused eval head: pool + 5 MLP layers + tanh ----------------
#define EVAL_SMEM ((64 * 132 + 128 * 128) * 4)
__global__ void eval_fused(const float* __restrict__ h, const float* __restrict__ ew,
                           const float* __restrict__ eb, const float* __restrict__ wo,
                           const float* __restrict__ bo, float* __restrict__ out)
{
    extern __shared__ float sm[];
    float* vbuf = sm;             // [64][132]
    float* wsm = sm + 64 * 132;   // [128][128]
    int t = threadIdx.x;
    int wid = t >> 5, lane = t & 31;
    int gbase = blockIdx.x * 64;

    // pool (skip node 0 of each graph, divide by 63)
    for (int q = 0; q < 8; ++q) {
        int gl = wid * 8 + q;
        int g = gbase + gl;
        float4 acc = make_float4(0.f, 0.f, 0.f, 0.f);
        const float4* hp = (const float4*)h + (size_t)g * 64 * 32 + lane;
        for (int j = 1; j < 64; ++j) {
            float4 v = hp[j * 32];
            acc.x += v.x; acc.y += v.y; acc.z += v.z; acc.w += v.w;
        }
        const float inv = 1.0f / 63.0f;
        vbuf[gl * 132 + lane * 4 + 0] = acc.x * inv;
        vbuf[gl * 132 + lane * 4 + 1] = acc.y * inv;
        vbuf[gl * 132 + lane * 4 + 2] = acc.z * inv;
        vbuf[gl * 132 + lane * 4 + 3] = acc.w * inv;
    }
    __syncthreads();

    int g = t >> 2;
    int c0 = (t & 3) * 32;
    for (int layer = 0; layer < 5; ++layer) {
        const float* W = ew + (size_t)layer * 16384;
#pragma unroll
        for (int p = 0; p < 16; ++p)
            ((float4*)wsm)[t + p * 256] = ((const float4*)W)[t + p * 256];
        __syncthreads();
        float acc[32];
#pragma unroll
        for (int c = 0; c < 32; ++c) acc[c] = eb[layer * 128 + c0 + c];
        for (int k = 0; k < 128; ++k) {
            float a = vbuf[g * 132 + k];
            const float* wr = wsm + k * 128 + c0;
#pragma unroll
            for (int c = 0; c < 32; ++c) acc[c] += a * wr[c];
        }
        __syncthreads();
#pragma unroll
        for (int c = 0; c < 32; ++c) vbuf[g * 132 + c0 + c] = fmaxf(acc[c], 0.f);
        __syncthreads();
    }

    float p = 0.f;
#pragma unroll
    for (int c = 0; c < 32; ++c) p += vbuf[g * 132 + c0 + c] * wo[c0 + c];
    p += __shfl_down_sync(0xffffffffu, p, 2, 4);
    p += __shfl_down_sync(0xffffffffu, p, 1, 4);
    if ((t & 3) == 0) out[gbase + g] = tanhf(p + bo[0]);
}

// ---------------- host ----------------
extern "C" void kernel_launch(void* const* d_in, const int* in_sizes, int n_in,
                              void* d_out, int out_size)
{
    (void)in_sizes; (void)n_in; (void)out_size;
    const int* nodes = (const int*)d_in[0];
    const int* snd = (const int*)d_in[1];
    const int* rcv = (const int*)d_in[2];
    const int* gsnd = (const int*)d_in[3];
    const int* grcv = (const int*)d_in[4];
    const float* emb = (const float*)d_in[6];
    const float* w1 = (const float*)d_in[7];
    const float* b1 = (const float*)d_in[8];
    const float* w2 = (const float*)d_in[9];
    const float* b2 = (const float*)d_in[10];
    const float* w3 = (const float*)d_in[11];
    const float* b3 = (const float*)d_in[12];
    const float* wl = (const float*)d_in[13];
    const float* bl = (const float*)d_in[14];
    const float* ew = (const float*)d_in[15];
    const float* eb = (const float*)d_in[16];
    const float* wo = (const float*)d_in[17];
    const float* bo = (const float*)d_in[18];
    float* out = (float*)d_out;

    float *h, *ta, *aa, *ag, *s1, *r1, *s2, *r2, *c1, *c2, *w13, *w23, *bv1, *bv2;
    int *sdeg, *rdeg, *gsd, *grd, *offm, *offg, *curm, *curg, *srcm, *srcg;
    cudaGetSymbolAddress((void**)&h, g_h);
    cudaGetSymbolAddress((void**)&ta, g_ta);
    cudaGetSymbolAddress((void**)&aa, g_aa);
    cudaGetSymbolAddress((void**)&ag, g_ag);
    cudaGetSymbolAddress((void**)&s1, g_s1);
    cudaGetSymbolAddress((void**)&r1, g_r1);
    cudaGetSymbolAddress((void**)&s2, g_s2);
    cudaGetSymbolAddress((void**)&r2, g_r2);
    cudaGetSymbolAddress((void**)&c1, g_c1);
    cudaGetSymbolAddress((void**)&c2, g_c2);
    cudaGetSymbolAddress((void**)&w13, g_w13);
    cudaGetSymbolAddress((void**)&w23, g_w23);
    cudaGetSymbolAddress((void**)&bv1, g_bv1);
    cudaGetSymbolAddress((void**)&bv2, g_bv2);
    cudaGetSymbolAddress((void**)&sdeg, g_sdeg);
    cudaGetSymbolAddress((void**)&rdeg, g_rdeg);
    cudaGetSymbolAddress((void**)&gsd, g_gsd);
    cudaGetSymbolAddress((void**)&grd, g_grd);
    cudaGetSymbolAddress((void**)&offm, g_offm);
    cudaGetSymbolAddress((void**)&offg, g_offg);
    cudaGetSymbolAddress((void**)&curm, g_curm);
    cudaGetSymbolAddress((void**)&curg, g_curg);
    cudaGetSymbolAddress((void**)&srcm, g_srcm);
    cudaGetSymbolAddress((void**)&srcg, g_srcg);

    cudaFuncSetAttribute(gemm128, cudaFuncAttributeMaxDynamicSharedMemorySize, GEMM_SMEM);
    cudaFuncSetAttribute(precompute_w, cudaFuncAttributeMaxDynamicSharedMemorySize, PREW_SMEM);
    cudaFuncSetAttribute(eval_fused, cudaFuncAttributeMaxDynamicSharedMemorySize, EVAL_SMEM);

    cudaMemsetAsync(sdeg, 0, NN * sizeof(int));
    cudaMemsetAsync(rdeg, 0, NN * sizeof(int));
    cudaMemsetAsync(gsd, 0, NN * sizeof(int));
    cudaMemsetAsync(grd, 0, NN * sizeof(int));
    cudaMemsetAsync(curm, 0, NN * sizeof(int));
    cudaMemsetAsync(curg, 0, NN * sizeof(int));

    embed_kernel<<<NN * 32 / 256, 256>>>(nodes, emb, h);
    deg_both<<<EE / 256, 256>>>(snd, rcv, gsnd, grcv, sdeg, rdeg, gsd, grd);
    norm_both<<<NN / 256, 256>>>(sdeg, rdeg, gsd, grd, s1, r1, s2, r2);
    scan_both<<<1, 1024>>>(rdeg, grd, offm, offg);
    fill_both<<<EE / 256, 256>>>(snd, rcv, gsnd, grcv, offm, offg, curm, curg, srcm, srcg);

    // layer 0 aggregation (placed here so ncu -s 5 -c 1 captures it)
    agg2_kernel<<<NN * 32 / 256, 256>>>(h, s1, s2, offm, rdeg, srcm, offg, grd, srcg, aa, ag);

    csum_kernel<<<NN / 256, 256>>>(s1, r1, s2, r2, offm, rdeg, srcm, offg, grd, srcg, c1, c2);
    precompute_w<<<14, 256, PREW_SMEM>>>(w1, w2, w3, b1, b2, w13, w23, bv1, bv2);

    for (int i = 0; i < 7; ++i) {
        if (i > 0)
            agg2_kernel<<<NN * 32 / 256, 256>>>(h, s1, s2, offm, rdeg, srcm,
                                                offg, grd, srcg, aa, ag);
        gemm128<<<NN / 64, 256, GEMM_SMEM>>>(aa, r1, ag, r2,
                                             w13 + (size_t)i * 16384,
                                             w23 + (size_t)i * 16384,
                                             b3 + i * 128, bv1 + i * 128, bv2 + i * 128,
                                             c1, c2, h, 1, 1);
    }

    // logit projection + edge dots
    gemm128<<<NN / 64, 256, GEMM_SMEM>>>(h, 0, 0, 0, wl, 0, bl, 0, 0, 0, 0, ta, 0, 0);
    logits_kernel<<<EE * 8 / 256, 256>>>(ta, snd, rcv, out);

    // eval head (fused)
    eval_fused<<<BB / 64, 256, EVAL_SMEM>>>(h, ew, eb, wo, bo, out + EE);
}

// round 5
// speedup vs baseline: 1.0369x; 1.0008x over previous
#include <cuda_runtime.h>
#include <math.h>

#define NN 65536
#define EE 2097152
#define EGG 524288
#define BB 1024

// ---------------- scratch (device globals; allocation-free) ----------------
__device__ __align__(16) float g_h[NN * 128];
__device__ __align__(16) float g_ta[NN * 128];
__device__ __align__(16) float g_aa[NN * 128];
__device__ __align__(16) float g_ag[NN * 128];
__device__ __align__(16) float g_s1[NN], g_r1[NN], g_s2[NN], g_r2[NN];
__device__ __align__(16) float g_c1[NN], g_c2[NN];
__device__ __align__(16) float g_w13[7 * 128 * 128];
__device__ __align__(16) float g_w23[7 * 128 * 128];
__device__ __align__(16) float g_bv1[7 * 128], g_bv2[7 * 128];
__device__ int g_sdeg[NN], g_rdeg[NN], g_gsd[NN], g_grd[NN];
__device__ int g_offm[NN], g_offg[NN], g_curm[NN], g_curg[NN];
__device__ int g_srcm[EE], g_srcg[EGG];

// ---------------- f32x2 helpers ----------------
__device__ __forceinline__ unsigned long long pack2(float x) {
    unsigned long long r;
    unsigned u = __float_as_uint(x);
    asm("mov.b64 %0, {%1, %1};" : "=l"(r) : "r"(u));
    return r;
}
__device__ __forceinline__ void fma2(unsigned long long& d, unsigned long long a,
                                     unsigned long long b) {
    asm("fma.rn.f32x2 %0, %1, %2, %0;" : "+l"(d) : "l"(a), "l"(b));
}
__device__ __forceinline__ float2 unpack2(unsigned long long v) {
    unsigned lo, hi;
    asm("mov.b64 {%0, %1}, %2;" : "=r"(lo), "=r"(hi) : "l"(v));
    float2 f;
    f.x = __uint_as_float(lo);
    f.y = __uint_as_float(hi);
    return f;
}

// ---------------- GEMM ----------------
// out[r,:] = act( (rsA[r]*A[r,:])@W + [ (rsA2[r]*A2[r,:])@W2 ]
//                 + bias + cr1[r]*bv1 + cr2[r]*bv2 )
#define GEMM_SMEM ((128 * 68 + 128 * 128) * 4)

__global__ void __launch_bounds__(256, 2) gemm128(
    const float* __restrict__ A, const float* __restrict__ rsA,
    const float* __restrict__ A2, const float* __restrict__ rsA2,
    const float* __restrict__ W, const float* __restrict__ W2,
    const float* __restrict__ bias,
    const float* __restrict__ bv1, const float* __restrict__ bv2,
    const float* __restrict__ cr1, const float* __restrict__ cr2,
    float* __restrict__ out, int dual, int relu)
{
    extern __shared__ float sm[];
    float* Ast = sm;              // [128][68]  A tile transposed (k-major)
    float* Ws = sm + 128 * 68;    // [128][128]
    const int tid = threadIdx.x;
    const int tx = tid & 15;
    const int ty = tid >> 4;
    const int row0 = blockIdx.x * 64;

    unsigned long long acc[4][4];
#pragma unroll
    for (int i = 0; i < 4; ++i)
#pragma unroll
        for (int j = 0; j < 4; ++j) acc[i][j] = 0ull;

    for (int stage = 0; stage <= dual; ++stage) {
        const float* Ac = stage ? A2 : A;
        const float* rs = stage ? rsA2 : rsA;
        const float* Wc = stage ? W2 : W;
        if (stage) __syncthreads();
        {
            int r = tid & 63;
            int k4b = tid >> 6;
            float rsv = rs ? rs[row0 + r] : 1.0f;
#pragma unroll
            for (int p = 0; p < 8; ++p) {
                int k4 = k4b + p * 4;
                float4 v = ((const float4*)Ac)[(size_t)(row0 + r) * 32 + k4];
                v.x *= rsv; v.y *= rsv; v.z *= rsv; v.w *= rsv;
                Ast[(k4 * 4 + 0) * 68 + r] = v.x;
                Ast[(k4 * 4 + 1) * 68 + r] = v.y;
                Ast[(k4 * 4 + 2) * 68 + r] = v.z;
                Ast[(k4 * 4 + 3) * 68 + r] = v.w;
            }
        }
#pragma unroll
        for (int p = 0; p < 16; ++p) {
            int i = tid + p * 256;
            ((float4*)Ws)[i] = ((const float4*)Wc)[i];
        }
        __syncthreads();

        const ulonglong2* Wu = (const ulonglong2*)Ws;
#pragma unroll 8
        for (int k = 0; k < 128; ++k) {
            float4 a4 = *(const float4*)(Ast + k * 68 + ty * 4);
            ulonglong2 q0 = Wu[k * 32 + tx];
            ulonglong2 q1 = Wu[k * 32 + 16 + tx];
            unsigned long long ap[4];
            ap[0] = pack2(a4.x); ap[1] = pack2(a4.y);
            ap[2] = pack2(a4.z); ap[3] = pack2(a4.w);
#pragma unroll
            for (int rr = 0; rr < 4; ++rr) {
                fma2(acc[rr][0], ap[rr], q0.x);
                fma2(acc[rr][1], ap[rr], q0.y);
                fma2(acc[rr][2], ap[rr], q1.x);
                fma2(acc[rr][3], ap[rr], q1.y);
            }
        }
    }

    float bb[8], v1[8], v2[8];
#pragma unroll
    for (int j = 0; j < 4; ++j) {
        bb[j] = bias[tx * 4 + j];
        bb[4 + j] = bias[64 + tx * 4 + j];
        v1[j] = bv1 ? bv1[tx * 4 + j] : 0.f;
        v1[4 + j] = bv1 ? bv1[64 + tx * 4 + j] : 0.f;
        v2[j] = bv2 ? bv2[tx * 4 + j] : 0.f;
        v2[4 + j] = bv2 ? bv2[64 + tx * 4 + j] : 0.f;
    }
#pragma unroll
    for (int rr = 0; rr < 4; ++rr) {
        int r = row0 + ty * 4 + rr;
        float c1 = cr1 ? cr1[r] : 0.f;
        float c2 = cr2 ? cr2[r] : 0.f;
        float2 p0 = unpack2(acc[rr][0]);
        float2 p1 = unpack2(acc[rr][1]);
        float2 p2 = unpack2(acc[rr][2]);
        float2 p3 = unpack2(acc[rr][3]);
        float o[8] = {p0.x, p0.y, p1.x, p1.y, p2.x, p2.y, p3.x, p3.y};
#pragma unroll
        for (int j = 0; j < 8; ++j) {
            o[j] += bb[j] + c1 * v1[j] + c2 * v2[j];
            if (relu) o[j] = fmaxf(o[j], 0.f);
        }
        ((float4*)out)[(size_t)r * 32 + tx] = make_float4(o[0], o[1], o[2], o[3]);
        ((float4*)out)[(size_t)r * 32 + 16 + tx] = make_float4(o[4], o[5], o[6], o[7]);
    }
}

// ---------------- graph preprocessing ----------------
__global__ void deg_both(const int* __restrict__ snd, const int* __restrict__ rcv,
                         const int* __restrict__ gsnd, const int* __restrict__ grcv,
                         int* sdeg, int* rdeg, int* gsd, int* grd)
{
    int e = blockIdx.x * blockDim.x + threadIdx.x;
    if (e < EE) {
        atomicAdd(&sdeg[snd[e]], 1);
        atomicAdd(&rdeg[rcv[e]], 1);
    }
    if (e < EGG) {
        atomicAdd(&gsd[gsnd[e]], 1);
        atomicAdd(&grd[grcv[e]], 1);
    }
}

__global__ void norm_both(const int* __restrict__ sdeg, const int* __restrict__ rdeg,
                          const int* __restrict__ gsd, const int* __restrict__ grd,
                          float* s1, float* r1, float* s2, float* r2)
{
    int i = blockIdx.x * blockDim.x + threadIdx.x;
    if (i >= NN) return;
    s1[i] = rsqrtf((float)(sdeg[i] + 1));
    r1[i] = rsqrtf((float)(rdeg[i] + 1));
    s2[i] = rsqrtf((float)(gsd[i] + 1));
    r2[i] = rsqrtf((float)(grd[i] + 1));
}

__device__ void scan_one(const int* __restrict__ x, int* __restrict__ off, int* part)
{
    int t = threadIdx.x;
    int base = t * 64;
    int s = 0;
#pragma unroll 8
    for (int j = 0; j < 64; ++j) s += x[base + j];
    part[t] = s;
    __syncthreads();
    for (int d = 1; d < 1024; d <<= 1) {
        int v = (t >= d) ? part[t - d] : 0;
        __syncthreads();
        part[t] += v;
        __syncthreads();
    }
    int run = t ? part[t - 1] : 0;
#pragma unroll 8
    for (int j = 0; j < 64; ++j) {
        off[base + j] = run;
        run += x[base + j];
    }
    __syncthreads();
}

__global__ void scan_both(const int* rdeg, const int* grd, int* offm, int* offg)
{
    __shared__ int part[1024];
    scan_one(rdeg, offm, part);
    scan_one(grd, offg, part);
}

__global__ void fill_both(const int* __restrict__ snd, const int* __restrict__ rcv,
                          const int* __restrict__ gsnd, const int* __restrict__ grcv,
                          const int* __restrict__ offm, const int* __restrict__ offg,
                          int* curm, int* curg, int* srcm, int* srcg)
{
    int e = blockIdx.x * blockDim.x + threadIdx.x;
    if (e < EE) {
        int r = rcv[e];
        srcm[offm[r] + atomicAdd(&curm[r], 1)] = snd[e];
    }
    if (e < EGG) {
        int r = grcv[e];
        srcg[offg[r] + atomicAdd(&curg[r], 1)] = gsnd[e];
    }
}

// c1[i] = r1[i]*(s1[i] + sum_src s1[src]);  likewise grid
__global__ void csum_kernel(const float* __restrict__ s1, const float* __restrict__ r1,
                            const float* __restrict__ s2, const float* __restrict__ r2,
                            const int* __restrict__ offm, const int* __restrict__ cntm,
                            const int* __restrict__ srcm,
                            const int* __restrict__ offg, const int* __restrict__ cntg,
                            const int* __restrict__ srcg,
                            float* __restrict__ c1, float* __restrict__ c2)
{
    int i = blockIdx.x * blockDim.x + threadIdx.x;
    if (i >= NN) return;
    float a = s1[i];
    int b = offm[i], n = cntm[i];
    for (int j = 0; j < n; ++j) a += s1[srcm[b + j]];
    c1[i] = r1[i] * a;
    float g = s2[i];
    b = offg[i]; n = cntg[i];
    for (int j = 0; j < n; ++j) g += s2[srcg[b + j]];
    c2[i] = r2[i] * g;
}

// ---------------- embed ----------------
__global__ void embed_kernel(const int* __restrict__ nodes,
                             const float* __restrict__ emb, float* __restrict__ h)
{
    int t = blockIdx.x * blockDim.x + threadIdx.x;
    int row = t >> 5, c = t & 31;
    ((float4*)h)[t] = ((const float4*)emb)[nodes[row] * 32 + c];
}

// ---------------- fused dual-graph aggregation ----------------
// am[i] = s1[i]*h[i] + sum_src s1[src]*h[src];  ag likewise with s2/grid CSR
__global__ void agg2_kernel(const float* __restrict__ h,
                            const float* __restrict__ s1, const float* __restrict__ s2,
                            const int* __restrict__ offm, const int* __restrict__ cntm,
                            const int* __restrict__ srcm,
                            const int* __restrict__ offg, const int* __restrict__ cntg,
                            const int* __restrict__ srcg,
                            float* __restrict__ am, float* __restrict__ ag)
{
    int w = (blockIdx.x * blockDim.x + threadIdx.x) >> 5;
    int lane = threadIdx.x & 31;
    if (w >= NN) return;
    const float4* h4 = (const float4*)h;
    float4 hv = h4[(size_t)w * 32 + lane];
    float si = s1[w], gi = s2[w];
    float4 A = make_float4(hv.x * si, hv.y * si, hv.z * si, hv.w * si);
    float4 G = make_float4(hv.x * gi, hv.y * gi, hv.z * gi, hv.w * gi);

    int beg = offm[w], n = cntm[w];
    int j = 0;
    for (; j + 4 <= n; j += 4) {
        int i0 = srcm[beg + j], i1 = srcm[beg + j + 1];
        int i2 = srcm[beg + j + 2], i3 = srcm[beg + j + 3];
        float f0 = s1[i0], f1 = s1[i1], f2 = s1[i2], f3 = s1[i3];
        float4 v0 = h4[(size_t)i0 * 32 + lane];
        float4 v1 = h4[(size_t)i1 * 32 + lane];
        float4 v2 = h4[(size_t)i2 * 32 + lane];
        float4 v3 = h4[(size_t)i3 * 32 + lane];
        A.x += f0 * v0.x + f1 * v1.x + f2 * v2.x + f3 * v3.x;
        A.y += f0 * v0.y + f1 * v1.y + f2 * v2.y + f3 * v3.y;
        A.z += f0 * v0.z + f1 * v1.z + f2 * v2.z + f3 * v3.z;
        A.w += f0 * v0.w + f1 * v1.w + f2 * v2.w + f3 * v3.w;
    }
    for (; j < n; ++j) {
        int i0 = srcm[beg + j];
        float f0 = s1[i0];
        float4 v0 = h4[(size_t)i0 * 32 + lane];
        A.x += f0 * v0.x; A.y += f0 * v0.y; A.z += f0 * v0.z; A.w += f0 * v0.w;
    }

    beg = offg[w]; n = cntg[w];
    j = 0;
    for (; j + 2 <= n; j += 2) {
        int i0 = srcg[beg + j], i1 = srcg[beg + j + 1];
        float f0 = s2[i0], f1 = s2[i1];
        float4 v0 = h4[(size_t)i0 * 32 + lane];
        float4 v1 = h4[(size_t)i1 * 32 + lane];
        G.x += f0 * v0.x + f1 * v1.x;
        G.y += f0 * v0.y + f1 * v1.y;
        G.z += f0 * v0.z + f1 * v1.z;
        G.w += f0 * v0.w + f1 * v1.w;
    }
    for (; j < n; ++j) {
        int i0 = srcg[beg + j];
        float f0 = s2[i0];
        float4 v0 = h4[(size_t)i0 * 32 + lane];
        G.x += f0 * v0.x; G.y += f0 * v0.y; G.z += f0 * v0.z; G.w += f0 * v0.w;
    }
    ((float4*)am)[(size_t)w * 32 + lane] = A;
    ((float4*)ag)[(size_t)w * 32 + lane] = G;
}

// ---------------- weight precompute: W13 = W1@W3a, W23 = W2@W3b, bv = b@W3x ----
#define PREW_SMEM (128 * 128 * 4)
__global__ void precompute_w(const float* __restrict__ w1, const float* __restrict__ w2,
                             const float* __restrict__ w3,
                             const float* __restrict__ b1, const float* __restrict__ b2,
                             float* __restrict__ w13, float* __restrict__ w23,
                             float* __restrict__ bv1, float* __restrict__ bv2)
{
    extern __shared__ float Bs[];
    int layer = blockIdx.x >> 1;
    int which = blockIdx.x & 1;
    const float* Aw = (which ? w2 : w1) + (size_t)layer * 16384;
    const float* Bw = w3 + (size_t)layer * 32768 + which * 16384;
    const float* bb = (which ? b2 : b1) + layer * 128;
    float* Cw = (which ? w23 : w13) + (size_t)layer * 16384;
    float* bv = (which ? bv2 : bv1) + layer * 128;
    int t = threadIdx.x;
#pragma unroll
    for (int p = 0; p < 16; ++p)
        ((float4*)Bs)[t + p * 256] = ((const float4*)Bw)[t + p * 256];
    __syncthreads();
    int k = t >> 1;
    int c0 = (t & 1) * 64;
    float acc[64];
#pragma unroll
    for (int c = 0; c < 64; ++c) acc[c] = 0.f;
    for (int j = 0; j < 128; ++j) {
        float a = Aw[k * 128 + j];
        const float* br = Bs + j * 128 + c0;
#pragma unroll
        for (int c = 0; c < 64; ++c) acc[c] += a * br[c];
    }
#pragma unroll
    for (int c = 0; c < 64; ++c) Cw[k * 128 + c0 + c] = acc[c];
    if (t < 128) {
        float a = 0.f;
        for (int j = 0; j < 128; ++j) a += bb[j] * Bs[j * 128 + t];
        bv[t] = a;
    }
}

// ---------------- logits ----------------
__global__ void logits_kernel(const float* __restrict__ lg, const int* __restrict__ snd,
                              const int* __restrict__ rcv, float* __restrict__ out)
{
    int t = blockIdx.x * blockDim.x + threadIdx.x;
    int e = t >> 3, g = t & 7;
    if (e >= EE) return;
    int s = snd[e], r = rcv[e];
    const float4* a = (const float4*)lg + (size_t)s * 32 + g * 4;
    const float4* b = (const float4*)lg + (size_t)r * 32 + g * 4;
    float acc = 0.f;
#pragma unroll
    for (int i = 0; i < 4; ++i) {
        float4 x = a[i], y = b[i];
        acc += x.x * y.x + x.y * y.y + x.z * y.z + x.w * y.w;
    }
    acc += __shfl_down_sync(0xffffffffu, acc, 4);
    acc += __shfl_down_sync(0xffffffffu, acc, 2);
    acc += __shfl_down_sync(0xffffffffu, acc, 1);
    if (g == 0) out[e] = acc;
}

// ---------------- fused eval head: pool + 5 MLP layers + tanh ----------------
#define EVAL_SMEM ((64 * 132 + 128 * 128) * 4)
__global__ void eval_fused(const float* __restrict__ h, const float* __restrict__ ew,
                           const float* __restrict__ eb, const float* __restrict__ wo,
                           const float* __restrict__ bo, float* __restrict__ out)
{
    extern __shared__ float sm[];
    float* vbuf = sm;             // [64][132]
    float* wsm = sm + 64 * 132;   // [128][128]
    int t = threadIdx.x;
    int wid = t >> 5, lane = t & 31;
    int gbase = blockIdx.x * 64;

    // pool (skip node 0 of each graph, divide by 63)
    for (int q = 0; q < 8; ++q) {
        int gl = wid * 8 + q;
        int g = gbase + gl;
        float4 acc = make_float4(0.f, 0.f, 0.f, 0.f);
        const float4* hp = (const float4*)h + (size_t)g * 64 * 32 + lane;
        for (int j = 1; j < 64; ++j) {
            float4 v = hp[j * 32];
            acc.x += v.x; acc.y += v.y; acc.z += v.z; acc.w += v.w;
        }
        const float inv = 1.0f / 63.0f;
        vbuf[gl * 132 + lane * 4 + 0] = acc.x * inv;
        vbuf[gl * 132 + lane * 4 + 1] = acc.y * inv;
        vbuf[gl * 132 + lane * 4 + 2] = acc.z * inv;
        vbuf[gl * 132 + lane * 4 + 3] = acc.w * inv;
    }
    __syncthreads();

    int g = t >> 2;
    int c0 = (t & 3) * 32;
    for (int layer = 0; layer < 5; ++layer) {
        const float* W = ew + (size_t)layer * 16384;
#pragma unroll
        for (int p = 0; p < 16; ++p)
            ((float4*)wsm)[t + p * 256] = ((const float4*)W)[t + p * 256];
        __syncthreads();
        float acc[32];
#pragma unroll
        for (int c = 0; c < 32; ++c) acc[c] = eb[layer * 128 + c0 + c];
        for (int k = 0; k < 128; ++k) {
            float a = vbuf[g * 132 + k];
            const float* wr = wsm + k * 128 + c0;
#pragma unroll
            for (int c = 0; c < 32; ++c) acc[c] += a * wr[c];
        }
        __syncthreads();
#pragma unroll
        for (int c = 0; c < 32; ++c) vbuf[g * 132 + c0 + c] = fmaxf(acc[c], 0.f);
        __syncthreads();
    }

    float p = 0.f;
#pragma unroll
    for (int c = 0; c < 32; ++c) p += vbuf[g * 132 + c0 + c] * wo[c0 + c];
    p += __shfl_down_sync(0xffffffffu, p, 2, 4);
    p += __shfl_down_sync(0xffffffffu, p, 1, 4);
    if ((t & 3) == 0) out[gbase + g] = tanhf(p + bo[0]);
}

// ---------------- host ----------------
extern "C" void kernel_launch(void* const* d_in, const int* in_sizes, int n_in,
                              void* d_out, int out_size)
{
    (void)in_sizes; (void)n_in; (void)out_size;
    const int* nodes = (const int*)d_in[0];
    const int* snd = (const int*)d_in[1];
    const int* rcv = (const int*)d_in[2];
    const int* gsnd = (const int*)d_in[3];
    const int* grcv = (const int*)d_in[4];
    const float* emb = (const float*)d_in[6];
    const float* w1 = (const float*)d_in[7];
    const float* b1 = (const float*)d_in[8];
    const float* w2 = (const float*)d_in[9];
    const float* b2 = (const float*)d_in[10];
    const float* w3 = (const float*)d_in[11];
    const float* b3 = (const float*)d_in[12];
    const float* wl = (const float*)d_in[13];
    const float* bl = (const float*)d_in[14];
    const float* ew = (const float*)d_in[15];
    const float* eb = (const float*)d_in[16];
    const float* wo = (const float*)d_in[17];
    const float* bo = (const float*)d_in[18];
    float* out = (float*)d_out;

    float *h, *ta, *aa, *ag, *s1, *r1, *s2, *r2, *c1, *c2, *w13, *w23, *bv1, *bv2;
    int *sdeg, *rdeg, *gsd, *grd, *offm, *offg, *curm, *curg, *srcm, *srcg;
    cudaGetSymbolAddress((void**)&h, g_h);
    cudaGetSymbolAddress((void**)&ta, g_ta);
    cudaGetSymbolAddress((void**)&aa, g_aa);
    cudaGetSymbolAddress((void**)&ag, g_ag);
    cudaGetSymbolAddress((void**)&s1, g_s1);
    cudaGetSymbolAddress((void**)&r1, g_r1);
    cudaGetSymbolAddress((void**)&s2, g_s2);
    cudaGetSymbolAddress((void**)&r2, g_r2);
    cudaGetSymbolAddress((void**)&c1, g_c1);
    cudaGetSymbolAddress((void**)&c2, g_c2);
    cudaGetSymbolAddress((void**)&w13, g_w13);
    cudaGetSymbolAddress((void**)&w23, g_w23);
    cudaGetSymbolAddress((void**)&bv1, g_bv1);
    cudaGetSymbolAddress((void**)&bv2, g_bv2);
    cudaGetSymbolAddress((void**)&sdeg, g_sdeg);
    cudaGetSymbolAddress((void**)&rdeg, g_rdeg);
    cudaGetSymbolAddress((void**)&gsd, g_gsd);
    cudaGetSymbolAddress((void**)&grd, g_grd);
    cudaGetSymbolAddress((void**)&offm, g_offm);
    cudaGetSymbolAddress((void**)&offg, g_offg);
    cudaGetSymbolAddress((void**)&curm, g_curm);
    cudaGetSymbolAddress((void**)&curg, g_curg);
    cudaGetSymbolAddress((void**)&srcm, g_srcm);
    cudaGetSymbolAddress((void**)&srcg, g_srcg);

    cudaFuncSetAttribute(gemm128, cudaFuncAttributeMaxDynamicSharedMemorySize, GEMM_SMEM);
    cudaFuncSetAttribute(precompute_w, cudaFuncAttributeMaxDynamicSharedMemorySize, PREW_SMEM);
    cudaFuncSetAttribute(eval_fused, cudaFuncAttributeMaxDynamicSharedMemorySize, EVAL_SMEM);

    cudaMemsetAsync(sdeg, 0, NN * sizeof(int));
    cudaMemsetAsync(rdeg, 0, NN * sizeof(int));
    cudaMemsetAsync(gsd, 0, NN * sizeof(int));
    cudaMemsetAsync(grd, 0, NN * sizeof(int));
    cudaMemsetAsync(curm, 0, NN * sizeof(int));
    cudaMemsetAsync(curg, 0, NN * sizeof(int));

    embed_kernel<<<NN * 32 / 256, 256>>>(nodes, emb, h);
    deg_both<<<EE / 256, 256>>>(snd, rcv, gsnd, grcv, sdeg, rdeg, gsd, grd);
    norm_both<<<NN / 256, 256>>>(sdeg, rdeg, gsd, grd, s1, r1, s2, r2);
    scan_both<<<1, 1024>>>(rdeg, grd, offm, offg);
    fill_both<<<EE / 256, 256>>>(snd, rcv, gsnd, grcv, offm, offg, curm, curg, srcm, srcg);

    // layer 0 aggregation (placed here so ncu -s 5 -c 1 captures it)
    agg2_kernel<<<NN * 32 / 256, 256>>>(h, s1, s2, offm, rdeg, srcm, offg, grd, srcg, aa, ag);

    csum_kernel<<<NN / 256, 256>>>(s1, r1, s2, r2, offm, rdeg, srcm, offg, grd, srcg, c1, c2);
    precompute_w<<<14, 256, PREW_SMEM>>>(w1, w2, w3, b1, b2, w13, w23, bv1, bv2);

    for (int i = 0; i < 7; ++i) {
        if (i > 0)
            agg2_kernel<<<NN * 32 / 256, 256>>>(h, s1, s2, offm, rdeg, srcm,
                                                offg, grd, srcg, aa, ag);
        gemm128<<<NN / 64, 256, GEMM_SMEM>>>(aa, r1, ag, r2,
                                             w13 + (size_t)i * 16384,
                                             w23 + (size_t)i * 16384,
                                             b3 + i * 128, bv1 + i * 128, bv2 + i * 128,
                                             c1, c2, h, 1, 1);
    }

    // logit projection + edge dots
    gemm128<<<NN / 64, 256, GEMM_SMEM>>>(h, 0, 0, 0, wl, 0, bl, 0, 0, 0, 0, ta, 0, 0);
    logits_kernel<<<EE * 8 / 256, 256>>>(ta, snd, rcv, out);

    // eval head (fused)
    eval_fused<<<BB / 64, 256, EVAL_SMEM>>>(h, ew, eb, wo, bo, out + EE);
}